// round 1
// baseline (speedup 1.0000x reference)
#include <cuda_runtime.h>
#include <math.h>

#define BATCH 32
#define CH    512
#define BC    (BATCH * CH)      // 16384
#define HW    3136              // 56*56
#define HW4   784               // HW / 4
#define KK    3
#define PADK  1

// scratch (allocation-free rule: __device__ globals)
__device__ float g_y[BC];
__device__ float g_attn[BC];

// ---------------------------------------------------------------------------
// Kernel 1: per-(b,c) spatial mean. One block per plane, float4 loads.
// ---------------------------------------------------------------------------
__global__ __launch_bounds__(256) void mean_kernel(const float* __restrict__ x) {
    const int bc = blockIdx.x;
    const float4* __restrict__ p = reinterpret_cast<const float4*>(x + (size_t)bc * HW);

    float s = 0.0f;
    #pragma unroll 4
    for (int i = threadIdx.x; i < HW4; i += 256) {
        float4 v = p[i];
        s += (v.x + v.y) + (v.z + v.w);
    }

    // warp reduce
    #pragma unroll
    for (int off = 16; off > 0; off >>= 1)
        s += __shfl_xor_sync(0xFFFFFFFFu, s, off);

    __shared__ float sm[8];
    const int wid = threadIdx.x >> 5;
    const int lid = threadIdx.x & 31;
    if (lid == 0) sm[wid] = s;
    __syncthreads();
    if (wid == 0) {
        float t = (lid < 8) ? sm[lid] : 0.0f;
        #pragma unroll
        for (int off = 4; off > 0; off >>= 1)
            t += __shfl_xor_sync(0xFFFFFFFFu, t, off);
        if (lid == 0) g_y[bc] = t * (1.0f / (float)HW);
    }
}

// ---------------------------------------------------------------------------
// Kernel 2: offset conv + deformable 1D sample + sigmoid gate.
// One block per batch, one thread per channel.
// ---------------------------------------------------------------------------
__global__ __launch_bounds__(CH) void attn_kernel(const float* __restrict__ w_offset,
                                                  const float* __restrict__ w_deform,
                                                  const float* __restrict__ b_deform) {
    const int b = blockIdx.x;
    const int c = threadIdx.x;

    __shared__ float ys[CH];
    __shared__ float wo[KK * KK];
    __shared__ float wd[KK];
    __shared__ float bd;

    ys[c] = g_y[b * CH + c];
    if (c < KK * KK) wo[c] = w_offset[c];
    if (c < KK)      wd[c] = w_deform[c];
    if (c == 0)      bd = b_deform[0];
    __syncthreads();

    float out = bd;
    #pragma unroll
    for (int k = 0; k < KK; k++) {
        // cross-correlation (XLA conv semantics), zero padding
        float off = 0.0f;
        #pragma unroll
        for (int j = 0; j < KK; j++) {
            int idx = c + j - PADK;
            float yv = (idx >= 0 && idx < CH) ? ys[idx] : 0.0f;
            off = fmaf(wo[k * KK + j], yv, off);
        }
        float pos  = (float)c + (float)(k - PADK) + off;
        float p0f  = floorf(pos);
        float frac = pos - p0f;
        int   p0   = (int)p0f;
        int   p1   = p0 + 1;
        float v0 = (p0 >= 0 && p0 < CH) ? ys[p0] : 0.0f;
        float v1 = (p1 >= 0 && p1 < CH) ? ys[p1] : 0.0f;
        out = fmaf(wd[k], fmaf(v1 - v0, frac, v0), out);
    }
    g_attn[b * CH + c] = 1.0f / (1.0f + expf(-out));
}

// ---------------------------------------------------------------------------
// Kernel 3: out = attn[b,c] * x, float4 streaming.
// ---------------------------------------------------------------------------
__global__ __launch_bounds__(256) void scale_kernel(const float* __restrict__ x,
                                                    float* __restrict__ out) {
    const int bc = blockIdx.x;
    const float a = g_attn[bc];
    const float4* __restrict__ xp = reinterpret_cast<const float4*>(x + (size_t)bc * HW);
    float4* __restrict__ op = reinterpret_cast<float4*>(out + (size_t)bc * HW);

    #pragma unroll 4
    for (int i = threadIdx.x; i < HW4; i += 256) {
        float4 v = xp[i];
        v.x *= a; v.y *= a; v.z *= a; v.w *= a;
        op[i] = v;
    }
}

extern "C" void kernel_launch(void* const* d_in, const int* in_sizes, int n_in,
                              void* d_out, int out_size) {
    const float* x        = (const float*)d_in[0];   // (32,512,56,56)
    const float* w_offset = (const float*)d_in[1];   // (3,1,3) = 9
    const float* w_deform = (const float*)d_in[2];   // (3,)
    const float* b_deform = (const float*)d_in[3];   // ()
    float* out = (float*)d_out;

    mean_kernel<<<BC, 256>>>(x);
    attn_kernel<<<BATCH, CH>>>(w_offset, w_deform, b_deform);
    scale_kernel<<<BC, 256>>>(x, out);
}

// round 2
// speedup vs baseline: 1.0449x; 1.0449x over previous
#include <cuda_runtime.h>
#include <math.h>

#define BATCH 32
#define CH    512
#define BC    (BATCH * CH)      // 16384
#define HW    3136              // 56*56
#define HW4   784               // HW / 4
#define KK    3
#define PADK  1

__device__ float g_y[BC];
__device__ float g_attn[BC];

// ---------------------------------------------------------------------------
// Kernel 1: per-(b,c) spatial mean. ONE WARP per plane: 24.5 float4/lane,
// deep MLP, warp-shuffle-only reduction (no smem, no __syncthreads).
// ---------------------------------------------------------------------------
__global__ __launch_bounds__(256) void mean_kernel(const float* __restrict__ x) {
    const int warp_global = (blockIdx.x * 8) + (threadIdx.x >> 5); // 8 warps/block
    const int lid = threadIdx.x & 31;
    if (warp_global >= BC) return;

    const float4* __restrict__ p = reinterpret_cast<const float4*>(x + (size_t)warp_global * HW);

    float s = 0.0f;
    // 784 = 24*32 + 16 : 24 full rounds, unrolled for MLP
    #pragma unroll 6
    for (int i = 0; i < 24; i++) {
        float4 v = p[i * 32 + lid];
        s += (v.x + v.y) + (v.z + v.w);
    }
    if (lid < 16) {
        float4 v = p[24 * 32 + lid];
        s += (v.x + v.y) + (v.z + v.w);
    }

    #pragma unroll
    for (int off = 16; off > 0; off >>= 1)
        s += __shfl_xor_sync(0xFFFFFFFFu, s, off);

    if (lid == 0) g_y[warp_global] = s * (1.0f / (float)HW);
}

// ---------------------------------------------------------------------------
// Kernel 2: offset conv + deformable 1D sample + sigmoid gate.
// One block per batch, one thread per channel. O(16K) work, microseconds.
// ---------------------------------------------------------------------------
__global__ __launch_bounds__(CH) void attn_kernel(const float* __restrict__ w_offset,
                                                  const float* __restrict__ w_deform,
                                                  const float* __restrict__ b_deform) {
    const int b = blockIdx.x;
    const int c = threadIdx.x;

    __shared__ float ys[CH];
    __shared__ float wo[KK * KK];
    __shared__ float wd[KK];
    __shared__ float bd;

    ys[c] = g_y[b * CH + c];
    if (c < KK * KK) wo[c] = w_offset[c];
    if (c < KK)      wd[c] = w_deform[c];
    if (c == 0)      bd = b_deform[0];
    __syncthreads();

    float out = bd;
    #pragma unroll
    for (int k = 0; k < KK; k++) {
        // cross-correlation (XLA conv semantics), zero padding
        float off = 0.0f;
        #pragma unroll
        for (int j = 0; j < KK; j++) {
            int idx = c + j - PADK;
            float yv = (idx >= 0 && idx < CH) ? ys[idx] : 0.0f;
            off = fmaf(wo[k * KK + j], yv, off);
        }
        float pos  = (float)c + (float)(k - PADK) + off;
        float p0f  = floorf(pos);
        float frac = pos - p0f;
        int   p0   = (int)p0f;
        int   p1   = p0 + 1;
        float v0 = (p0 >= 0 && p0 < CH) ? ys[p0] : 0.0f;
        float v1 = (p1 >= 0 && p1 < CH) ? ys[p1] : 0.0f;
        out = fmaf(wd[k], fmaf(v1 - v0, frac, v0), out);
    }
    g_attn[b * CH + c] = 1.0f / (1.0f + expf(-out));
}

// ---------------------------------------------------------------------------
// Kernel 3: out = attn[b,c] * x, float4 streaming. __ldcs/__stcs: neither
// the x re-read nor the output has any reuse — keep them out of L2's way.
// ---------------------------------------------------------------------------
__global__ __launch_bounds__(256) void scale_kernel(const float* __restrict__ x,
                                                    float* __restrict__ out) {
    const int bc = blockIdx.x;
    const float a = g_attn[bc];
    const float4* __restrict__ xp = reinterpret_cast<const float4*>(x + (size_t)bc * HW);
    float4* __restrict__ op = reinterpret_cast<float4*>(out + (size_t)bc * HW);

    #pragma unroll 4
    for (int i = threadIdx.x; i < HW4; i += 256) {
        float4 v = __ldcs(&xp[i]);
        v.x *= a; v.y *= a; v.z *= a; v.w *= a;
        __stcs(&op[i], v);
    }
}

extern "C" void kernel_launch(void* const* d_in, const int* in_sizes, int n_in,
                              void* d_out, int out_size) {
    const float* x        = (const float*)d_in[0];   // (32,512,56,56)
    const float* w_offset = (const float*)d_in[1];   // (3,1,3) = 9
    const float* w_deform = (const float*)d_in[2];   // (3,)
    const float* b_deform = (const float*)d_in[3];   // ()
    float* out = (float*)d_out;

    mean_kernel<<<BC / 8, 256>>>(x);
    attn_kernel<<<BATCH, CH>>>(w_offset, w_deform, b_deform);
    scale_kernel<<<BC, 256>>>(x, out);
}

// round 3
// speedup vs baseline: 1.0835x; 1.0370x over previous
#include <cuda_runtime.h>
#include <math.h>

#define BATCH 32
#define CH    512
#define BC    (BATCH * CH)      // 16384
#define HW    3136              // 56*56
#define HW4   784               // HW / 4
#define KK    3
#define PADK  1

__device__ float g_y[BC];
__device__ float g_attn[BC];

// ---------------------------------------------------------------------------
// Kernel 1: per-(b,c) spatial mean. One warp per plane, warp-shuffle reduce.
// Default cache policy: we WANT x resident in L2 for scale_kernel's reuse.
// ---------------------------------------------------------------------------
__global__ __launch_bounds__(256) void mean_kernel(const float* __restrict__ x) {
    const int warp_global = (blockIdx.x * 8) + (threadIdx.x >> 5); // 8 warps/block
    const int lid = threadIdx.x & 31;

    const float4* __restrict__ p = reinterpret_cast<const float4*>(x + (size_t)warp_global * HW);

    float s = 0.0f;
    // 784 = 24*32 + 16
    #pragma unroll 8
    for (int i = 0; i < 24; i++) {
        float4 v = p[i * 32 + lid];
        s += (v.x + v.y) + (v.z + v.w);
    }
    if (lid < 16) {
        float4 v = p[24 * 32 + lid];
        s += (v.x + v.y) + (v.z + v.w);
    }

    #pragma unroll
    for (int off = 16; off > 0; off >>= 1)
        s += __shfl_xor_sync(0xFFFFFFFFu, s, off);

    if (lid == 0) g_y[warp_global] = s * (1.0f / (float)HW);
}

// ---------------------------------------------------------------------------
// Kernel 2: offset conv + deformable 1D sample + sigmoid gate.
// ---------------------------------------------------------------------------
__global__ __launch_bounds__(CH) void attn_kernel(const float* __restrict__ w_offset,
                                                  const float* __restrict__ w_deform,
                                                  const float* __restrict__ b_deform) {
    const int b = blockIdx.x;
    const int c = threadIdx.x;

    __shared__ float ys[CH];
    __shared__ float wo[KK * KK];
    __shared__ float wd[KK];
    __shared__ float bd;

    ys[c] = g_y[b * CH + c];
    if (c < KK * KK) wo[c] = w_offset[c];
    if (c < KK)      wd[c] = w_deform[c];
    if (c == 0)      bd = b_deform[0];
    __syncthreads();

    float out = bd;
    #pragma unroll
    for (int k = 0; k < KK; k++) {
        // cross-correlation (XLA conv semantics), zero padding
        float off = 0.0f;
        #pragma unroll
        for (int j = 0; j < KK; j++) {
            int idx = c + j - PADK;
            float yv = (idx >= 0 && idx < CH) ? ys[idx] : 0.0f;
            off = fmaf(wo[k * KK + j], yv, off);
        }
        float pos  = (float)c + (float)(k - PADK) + off;
        float p0f  = floorf(pos);
        float frac = pos - p0f;
        int   p0   = (int)p0f;
        int   p1   = p0 + 1;
        float v0 = (p0 >= 0 && p0 < CH) ? ys[p0] : 0.0f;
        float v1 = (p1 >= 0 && p1 < CH) ? ys[p1] : 0.0f;
        out = fmaf(wd[k], fmaf(v1 - v0, frac, v0), out);
    }
    g_attn[b * CH + c] = 1.0f / (1.0f + expf(-out));
}

// ---------------------------------------------------------------------------
// Kernel 3: out = attn[b,c] * x. REVERSE plane order: mean_kernel streamed
// planes 0..16383, so L2 (~126MB) holds the tail of x. Reading the tail
// first (LIFO) converts ~126MB of this pass's reads into L2 hits.
// __ldcs/__stcs mark scale's own traffic evict-first so it doesn't evict
// the resident x data prematurely.
// ---------------------------------------------------------------------------
__global__ __launch_bounds__(256) void scale_kernel(const float* __restrict__ x,
                                                    float* __restrict__ out) {
    const int bc = BC - 1 - blockIdx.x;      // reverse order for L2 reuse
    const float a = g_attn[bc];
    const float4* __restrict__ xp = reinterpret_cast<const float4*>(x + (size_t)bc * HW);
    float4* __restrict__ op = reinterpret_cast<float4*>(out + (size_t)bc * HW);

    #pragma unroll 4
    for (int i = threadIdx.x; i < HW4; i += 256) {
        float4 v = __ldcs(&xp[i]);
        v.x *= a; v.y *= a; v.z *= a; v.w *= a;
        __stcs(&op[i], v);
    }
}

extern "C" void kernel_launch(void* const* d_in, const int* in_sizes, int n_in,
                              void* d_out, int out_size) {
    const float* x        = (const float*)d_in[0];   // (32,512,56,56)
    const float* w_offset = (const float*)d_in[1];   // (3,1,3) = 9
    const float* w_deform = (const float*)d_in[2];   // (3,)
    const float* b_deform = (const float*)d_in[3];   // ()
    float* out = (float*)d_out;

    mean_kernel<<<BC / 8, 256>>>(x);
    attn_kernel<<<BATCH, CH>>>(w_offset, w_deform, b_deform);
    scale_kernel<<<BC, 256>>>(x, out);
}